// round 10
// baseline (speedup 1.0000x reference)
#include <cuda_runtime.h>

#define BATCHN 8192
#define SEQ 100
#define EMBED 50
#define HID 20
#define NLABEL 15
#define G3 60
#define VOCAB 50000

typedef unsigned long long ull;

// scratch: PW1[v] = emb[v] @ W1 + b1_input, pair-col-packed (col j, col j+32)
__device__ ull d_PW1p[(size_t)VOCAB * 32];

__device__ __forceinline__ ull pack2(float x) {
    ull d; asm("mov.b64 %0, {%1, %1};" : "=l"(d) : "f"(x)); return d;
}
__device__ __forceinline__ ull packab(float a, float b) {
    ull d; asm("mov.b64 %0, {%1, %2};" : "=l"(d) : "f"(a), "f"(b)); return d;
}
__device__ __forceinline__ void unpk(ull v, float &a, float &b) {
    asm("mov.b64 {%0, %1}, %2;" : "=f"(a), "=f"(b) : "l"(v));
}
__device__ __forceinline__ ull ffma2(ull a, ull b, ull c) {
    ull d; asm("fma.rn.f32x2 %0, %1, %2, %3;" : "=l"(d) : "l"(a), "l"(b), "l"(c)); return d;
}
__device__ __forceinline__ ull add2(ull a, ull b) {
    ull d; asm("add.rn.f32x2 %0, %1, %2;" : "=l"(d) : "l"(a), "l"(b)); return d;
}
__device__ __forceinline__ float sigm(float x) {
    return __fdividef(1.f, 1.f + __expf(-x));
}
__device__ __forceinline__ float tanh_(float x) {
    return 2.f * __fdividef(1.f, 1.f + __expf(-2.f * x)) - 1.f;
}

// ============================================================================
// proj: PW1[v] = emb[v]@W1 + bi1 (block-tiled, coalesced)
// ============================================================================
__global__ void __launch_bounds__(128) proj1_kernel(
    const float* __restrict__ emb, const float* __restrict__ W1,
    const float* __restrict__ b1)
{
    __shared__ __align__(16) ull sx[32 * EMBED];
    const int tid = threadIdx.x;
    const int w = tid >> 5, j = tid & 31;

    ull w1r[EMBED];
    #pragma unroll
    for (int k = 0; k < EMBED; k++) {
        float lo = W1[k * G3 + j];
        float hi = (j + 32 < G3) ? W1[k * G3 + j + 32] : 0.f;
        w1r[k] = packab(lo, hi);
    }
    const ull bias = packab(b1[j], (j + 32 < G3) ? b1[j + 32] : 0.f);

    const int ntiles = (VOCAB + 31) / 32;
    for (int tile = blockIdx.x; tile < ntiles; tile += gridDim.x) {
        const int row0 = tile * 32;
        const int nrow = (VOCAB - row0 < 32) ? (VOCAB - row0) : 32;
        for (int i = tid; i < nrow * EMBED; i += 128)
            sx[i] = pack2(emb[(size_t)row0 * EMBED + i]);
        __syncthreads();
        #pragma unroll
        for (int rr = 0; rr < 8; rr++) {
            int lr = w * 8 + rr;
            if (row0 + lr < VOCAB) {
                ull acc = bias;
                #pragma unroll
                for (int k = 0; k < EMBED; k += 2) {
                    ulonglong2 xv = *(const ulonglong2*)&sx[lr * EMBED + k];
                    acc = ffma2(xv.x, w1r[k], acc);
                    acc = ffma2(xv.y, w1r[k + 1], acc);
                }
                d_PW1p[(size_t)(row0 + lr) * 32 + j] = acc;
            }
        }
        __syncthreads();
    }
}

// ============================================================================
// Gate evaluation for one (q, i) unit: reads batch-paired sums, writes h
// dup-packed per element (two STS.64).
// ============================================================================
__device__ __forceinline__ void gate_unit(
    const ull* __restrict__ ssg, const ull* __restrict__ smhg,
    ull* __restrict__ shg, int q, int i, float &hpa, float &hpb)
{
    float z0, z1, r0, r1, x0, x1, m0, m1;
    unpk(ssg[q * 64 + i],      z0, z1);
    unpk(ssg[q * 64 + i + 20], r0, r1);
    unpk(ssg[q * 64 + i + 40], x0, x1);
    unpk(smhg[q * 24 + i],     m0, m1);
    float za = sigm(z0), zb = sigm(z1);
    float ra = sigm(r0), rb = sigm(r1);
    float ha = tanh_(fmaf(ra, m0, x0));
    float hb = tanh_(fmaf(rb, m1, x1));
    float n0 = fmaf(za, hpa - ha, ha);
    float n1 = fmaf(zb, hpb - hb, hb);
    hpa = n0; hpb = n1;
    shg[(2 * q) * HID + i]     = pack2(n0);
    shg[(2 * q + 1) * HID + i] = pack2(n1);
}

// ============================================================================
// Fused 2-layer GRU. E=8/warp: 16 col-lanes x 2 batch-groups; h dup-packed
// per element; weights used directly as (lo,hi) LDS.64 pairs (no dup MOVs).
// One warp per block, 1024 blocks, syncwarp-only.
// ============================================================================
__global__ void __launch_bounds__(32) wordrnn_kernel(
    const int* __restrict__ xg,
    const float* __restrict__ U1f, const float* __restrict__ b1,
    const float* __restrict__ W2f, const float* __restrict__ b2,
    const float* __restrict__ U2f,
    const float* __restrict__ Wd, const float* __restrict__ bd,
    float* __restrict__ out)
{
    __shared__ ull sU1[HID][32];                  // (M[k][c], M[k][c+32])
    __shared__ ull sW2[HID][32];
    __shared__ ull sU2[HID][32];
    __shared__ __align__(16) ull sh1[2][4][HID];  // [group][elem][k] = dup h
    __shared__ __align__(16) ull sh2[2][4][HID];
    __shared__ ull ss[2][2][64];                  // batch-paired gate sums
    __shared__ ull smh[2][2][24];                 // h-gate recurrent part
    __shared__ int sxi[8][SEQ];

    const int l = threadIdx.x;
    const int g = l >> 4, lc = l & 15;
    const int b0 = blockIdx.x * 8;

    // stage weights (pair-packed (c, c+32))
    for (int i = l; i < HID * 32; i += 32) {
        int k = i >> 5, c = i & 31;
        bool ok = (c + 32 < G3);
        int ch = ok ? c + 32 : 0;
        sU1[k][c] = packab(U1f[k * G3 + c], ok ? U1f[k * G3 + ch] : 0.f);
        sW2[k][c] = packab(W2f[k * G3 + c], ok ? W2f[k * G3 + ch] : 0.f);
        sU2[k][c] = packab(U2f[k * G3 + c], ok ? U2f[k * G3 + ch] : 0.f);
    }
    // stage indices: 8 rows x 100
    for (int i = l; i < 8 * 25; i += 32) {
        int r = i / 25, c = i % 25;
        *(int4*)&sxi[r][c * 4] = *(const int4*)(xg + (size_t)(b0 + r) * SEQ + c * 4);
    }
    for (int i = l; i < 2 * 4 * HID; i += 32) {
        ((ull*)sh1)[i] = 0ull;
        ((ull*)sh2)[i] = 0ull;
    }
    __syncwarp();

    // col pairs owned by this lane: p0 = lc (cols lc, lc+32), p1 = lc+16
    const int p0 = lc, p1 = lc + 16;
    const bool h1ok = (lc + 48 < G3);
    // biases, col-pair packed (lo, hi)
    const ull br1A = packab(b1[G3 + p0], b1[G3 + p0 + 32]);
    const ull br1B = packab(b1[G3 + p1], h1ok ? b1[G3 + p1 + 32] : 0.f);
    const ull bi2A = packab(b2[p0],      b2[p0 + 32]);
    const ull bi2B = packab(b2[p1],      h1ok ? b2[p1 + 32] : 0.f);
    const ull br2A = packab(b2[G3 + p0], b2[G3 + p0 + 32]);
    const ull br2B = packab(b2[G3 + p1], h1ok ? b2[G3 + p1 + 32] : 0.f);

    // hprev per gate round (3 rounds; 2 elems each)
    float hp1[3][2] = {{0.f,0.f},{0.f,0.f},{0.f,0.f}};
    float hp2[3][2] = {{0.f,0.f},{0.f,0.f},{0.f,0.f}};
    const int q1r = (lc >= 4) ? 1 : 0;
    const int i1r = (lc < 4) ? 16 + lc : lc - 4;

    const ull* __restrict__ pw0 = d_PW1p + p0;
    const ull* __restrict__ pw1 = d_PW1p + p1;

    // t=0 input projection: raw per-element gathers (no transpose needed)
    ull ax0[4], ax1[4];
    #pragma unroll
    for (int e = 0; e < 4; e++) {
        size_t ix = (size_t)sxi[4 * g + e][0] * 32;
        ax0[e] = __ldg(pw0 + ix);
        ax1[e] = __ldg(pw1 + ix);
    }

    for (int t = 0; t < SEQ; t++) {
        // ================= layer 1: a = h1 @ U1 + br1 =================
        ull a0[4], a1[4];
        #pragma unroll
        for (int e = 0; e < 4; e++) { a0[e] = br1A; a1[e] = br1B; }
        #pragma unroll
        for (int kp = 0; kp < HID / 2; kp++) {
            const int k = kp * 2;
            ull w00 = sU1[k][lc],     w01 = sU1[k][lc + 16];
            ull w10 = sU1[k + 1][lc], w11 = sU1[k + 1][lc + 16];
            #pragma unroll
            for (int e = 0; e < 4; e++) {
                ulonglong2 hv = *(const ulonglong2*)&sh1[g][e][k];
                a0[e] = ffma2(hv.x, w00, a0[e]);
                a1[e] = ffma2(hv.x, w01, a1[e]);
                a0[e] = ffma2(hv.y, w10, a0[e]);
                a1[e] = ffma2(hv.y, w11, a1[e]);
            }
        }
        // epilogue: 2x2 transpose to batch-pairs, scatter to ss/smh
        #pragma unroll
        for (int q = 0; q < 2; q++) {
            const int e0 = 2 * q, e1 = 2 * q + 1;
            float xa, xb, xc, xd, aa, ab, ac, ad;
            unpk(ax0[e0], xa, xb); unpk(ax0[e1], xc, xd);
            unpk(a0[e0],  aa, ab); unpk(a0[e1],  ac, ad);
            ss[g][q][lc] = add2(packab(xa, xc), packab(aa, ac));
            if (lc < 8) ss[g][q][lc + 32] = add2(packab(xb, xd), packab(ab, ad));
            else { ss[g][q][lc + 32] = packab(xb, xd); smh[g][q][lc - 8] = packab(ab, ad); }
            unpk(ax1[e0], xa, xb); unpk(ax1[e1], xc, xd);
            unpk(a1[e0],  aa, ab); unpk(a1[e1],  ac, ad);
            ss[g][q][lc + 16] = add2(packab(xa, xc), packab(aa, ac));
            ss[g][q][lc + 48] = packab(xb, xd);
            smh[g][q][lc + 8] = packab(ab, ad);
        }
        __syncwarp();
        {
            const ull* ssg  = &ss[g][0][0];
            const ull* smhg = &smh[g][0][0];
            ull* shg = &sh1[g][0][0];
            gate_unit(ssg, smhg, shg, 0, lc, hp1[0][0], hp1[0][1]);
            gate_unit(ssg, smhg, shg, q1r, i1r, hp1[1][0], hp1[1][1]);
            if (lc < 8) gate_unit(ssg, smhg, shg, 1, 12 + lc, hp1[2][0], hp1[2][1]);
        }
        __syncwarp();

        // prefetch next step's input projection (raw; covered by layer 2)
        if (t + 1 < SEQ) {
            #pragma unroll
            for (int e = 0; e < 4; e++) {
                size_t ix = (size_t)sxi[4 * g + e][t + 1] * 32;
                ax0[e] = __ldg(pw0 + ix);
                ax1[e] = __ldg(pw1 + ix);
            }
        }

        // ===== layer 2: m = h1@W2 + bi2 ; c = h2@U2 + br2 =====
        ull m0[4], m1[4], c0[4], c1[4];
        #pragma unroll
        for (int e = 0; e < 4; e++) { m0[e] = bi2A; m1[e] = bi2B; c0[e] = br2A; c1[e] = br2B; }
        #pragma unroll
        for (int kp = 0; kp < HID / 2; kp++) {
            const int k = kp * 2;
            ull wA0 = sW2[k][lc],     wA1 = sW2[k][lc + 16];
            ull wB0 = sW2[k + 1][lc], wB1 = sW2[k + 1][lc + 16];
            ull uA0 = sU2[k][lc],     uA1 = sU2[k][lc + 16];
            ull uB0 = sU2[k + 1][lc], uB1 = sU2[k + 1][lc + 16];
            #pragma unroll
            for (int e = 0; e < 4; e++) {
                ulonglong2 h1v = *(const ulonglong2*)&sh1[g][e][k];
                ulonglong2 h2v = *(const ulonglong2*)&sh2[g][e][k];
                m0[e] = ffma2(h1v.x, wA0, m0[e]);
                m1[e] = ffma2(h1v.x, wA1, m1[e]);
                c0[e] = ffma2(h2v.x, uA0, c0[e]);
                c1[e] = ffma2(h2v.x, uA1, c1[e]);
                m0[e] = ffma2(h1v.y, wB0, m0[e]);
                m1[e] = ffma2(h1v.y, wB1, m1[e]);
                c0[e] = ffma2(h2v.y, uB0, c0[e]);
                c1[e] = ffma2(h2v.y, uB1, c1[e]);
            }
        }
        #pragma unroll
        for (int q = 0; q < 2; q++) {
            const int e0 = 2 * q, e1 = 2 * q + 1;
            float ma, mb, mc, md, ca, cb, cc, cd;
            unpk(m0[e0], ma, mb); unpk(m0[e1], mc, md);
            unpk(c0[e0], ca, cb); unpk(c0[e1], cc, cd);
            ss[g][q][lc] = add2(packab(ma, mc), packab(ca, cc));
            if (lc < 8) ss[g][q][lc + 32] = add2(packab(mb, md), packab(cb, cd));
            else { ss[g][q][lc + 32] = packab(mb, md); smh[g][q][lc - 8] = packab(cb, cd); }
            unpk(m1[e0], ma, mb); unpk(m1[e1], mc, md);
            unpk(c1[e0], ca, cb); unpk(c1[e1], cc, cd);
            ss[g][q][lc + 16] = add2(packab(ma, mc), packab(ca, cc));
            ss[g][q][lc + 48] = packab(mb, md);
            smh[g][q][lc + 8] = packab(cb, cd);
        }
        __syncwarp();
        {
            const ull* ssg  = &ss[g][0][0];
            const ull* smhg = &smh[g][0][0];
            ull* shg = &sh2[g][0][0];
            gate_unit(ssg, smhg, shg, 0, lc, hp2[0][0], hp2[0][1]);
            gate_unit(ssg, smhg, shg, q1r, i1r, hp2[1][0], hp2[1][1]);
            if (lc < 8) gate_unit(ssg, smhg, shg, 1, 12 + lc, hp2[2][0], hp2[2][1]);
        }
        __syncwarp();
    }

    // ---- dense head: logits = h2 @ Wd + bd (h2 lo halves from dup store) ----
    if (lc < NLABEL) {
        #pragma unroll
        for (int e = 0; e < 4; e++) {
            float acc = bd[lc];
            #pragma unroll
            for (int k = 0; k < HID; k++) {
                float hv = ((const float*)&sh2[g][e][k])[0];
                acc = fmaf(hv, Wd[k * NLABEL + lc], acc);
            }
            out[(size_t)(b0 + 4 * g + e) * NLABEL + lc] = acc;
        }
    }
}

extern "C" void kernel_launch(void* const* d_in, const int* in_sizes, int n_in,
                              void* d_out, int out_size) {
    const int*   x   = (const int*)d_in[0];
    const float* emb = (const float*)d_in[1];
    const float* W1  = (const float*)d_in[2];
    const float* U1  = (const float*)d_in[3];
    const float* b1  = (const float*)d_in[4];
    const float* W2  = (const float*)d_in[5];
    const float* U2  = (const float*)d_in[6];
    const float* b2  = (const float*)d_in[7];
    const float* Wd  = (const float*)d_in[8];
    const float* bd  = (const float*)d_in[9];
    (void)in_sizes; (void)n_in; (void)out_size;

    proj1_kernel<<<512, 128>>>(emb, W1, b1);
    wordrnn_kernel<<<BATCHN / 8, 32>>>(
        x, U1, b1, W2, b2, U2, Wd, bd, (float*)d_out);
}